// round 2
// baseline (speedup 1.0000x reference)
#include <cuda_runtime.h>
#include <math.h>

// Problem constants
#define NB    2
#define NL    2048
#define NH    16
#define ND    64
#define NDIM  1024
#define NC    8
#define NPC   256
#define NG    16
#define NBC   (NB*NC)

// Scratch (device globals; no allocation allowed)
__device__ float g_q  [NB*NH*NL*ND];
__device__ float g_k  [NB*NH*NL*ND];
__device__ float g_v  [NB*NH*NL*ND];
__device__ float g_Mq [NBC*NPC*NG*16];
__device__ float g_Mkv[NBC*NPC*NG*16];
__device__ float g_Mo [NBC*NPC*NG*16];
__device__ float g_P  [NBC*16];
__device__ float g_Pi [NBC*16];
__device__ float g_y  [NB*NL*NDIM];

// ---------------------------------------------------------------------------
// Kernel 1: per-camera P = K4 @ viewmat and analytic P^{-1}
// P^{-1} = V^{-1} K4^{-1}; V = [R t; 0 1] -> V^{-1} = [R^T -R^T t; 0 1];
// K = [[f,0,cx],[0,f,cy],[0,0,1]] -> K^{-1} analytic.
// ---------------------------------------------------------------------------
__global__ void cam_kernel(const float* __restrict__ vm, const float* __restrict__ Kin) {
    int t = threadIdx.x;
    if (t >= NBC) return;
    const float* V = vm + t * 16;
    const float* K = Kin + t * 9;
    float P[16];
#pragma unroll
    for (int i = 0; i < 3; i++)
#pragma unroll
        for (int j = 0; j < 4; j++)
            P[i*4+j] = K[i*3+0]*V[0+j] + K[i*3+1]*V[4+j] + K[i*3+2]*V[8+j];
    P[12] = V[12]; P[13] = V[13]; P[14] = V[14]; P[15] = V[15];

    float Vi[16];
#pragma unroll
    for (int i = 0; i < 3; i++) {
#pragma unroll
        for (int j = 0; j < 3; j++) Vi[i*4+j] = V[j*4+i];
        Vi[i*4+3] = -(V[0*4+i]*V[3] + V[1*4+i]*V[7] + V[2*4+i]*V[11]);
    }
    Vi[12] = 0.f; Vi[13] = 0.f; Vi[14] = 0.f; Vi[15] = 1.f;

    float f = K[0], cx = K[2], cy = K[5];
    float invf = 1.0f / f;
    float Pi[16];
#pragma unroll
    for (int i = 0; i < 4; i++) {
        float c0 = Vi[i*4+0] * invf;
        float c1 = Vi[i*4+1] * invf;
        Pi[i*4+0] = c0;
        Pi[i*4+1] = c1;
        Pi[i*4+2] = Vi[i*4+2] - cx*c0 - cy*c1;
        Pi[i*4+3] = Vi[i*4+3];
    }
#pragma unroll
    for (int i = 0; i < 16; i++) { g_P[t*16+i] = P[i]; g_Pi[t*16+i] = Pi[i]; }
}

// ---------------------------------------------------------------------------
// Kernel 2: per-(b,c,p,g) 4x4 transforms Mq = P^{-T} D, Mkv = P D, Mo = D^T P^{-1}
// D = blockdiag(rot2(u*w_g), rot2(v*w_g))
// ---------------------------------------------------------------------------
__global__ void m_kernel() {
    int i = blockIdx.x * blockDim.x + threadIdx.x;   // < 65536
    int g  = i & 15;
    int p  = (i >> 4) & 255;
    int bc = i >> 12;                                // b*8 + c
    const float* P  = g_P  + bc * 16;
    const float* Pi = g_Pi + bc * 16;

    float u = ((p & 15) + 0.5f) * 16.0f;
    float v = ((p >> 4) + 0.5f) * 16.0f;
    float fr = powf(10000.0f, -(float)g / 16.0f);
    float sa, ca, sb, cb;
    sincosf(u * fr, &sa, &ca);
    sincosf(v * fr, &sb, &cb);

    float* mq  = g_Mq  + i * 16;
    float* mkv = g_Mkv + i * 16;
    float* mo  = g_Mo  + i * 16;
#pragma unroll
    for (int r = 0; r < 4; r++) {
        // Mq[r][k] = sum_j Pi[j][r] * D[j][k]
        float p0 = Pi[0*4+r], p1 = Pi[1*4+r], p2 = Pi[2*4+r], p3 = Pi[3*4+r];
        mq[r*4+0] =  p0*ca + p1*sa;
        mq[r*4+1] = -p0*sa + p1*ca;
        mq[r*4+2] =  p2*cb + p3*sb;
        mq[r*4+3] = -p2*sb + p3*cb;
        // Mkv[r][k] = sum_j P[r][j] * D[j][k]
        float q0 = P[r*4+0], q1 = P[r*4+1], q2 = P[r*4+2], q3 = P[r*4+3];
        mkv[r*4+0] =  q0*ca + q1*sa;
        mkv[r*4+1] = -q0*sa + q1*ca;
        mkv[r*4+2] =  q2*cb + q3*sb;
        mkv[r*4+3] = -q2*sb + q3*cb;
    }
#pragma unroll
    for (int k = 0; k < 4; k++) {
        // Mo[i][k] = sum_j D[j][i] * Pi[j][k]
        float p0 = Pi[0*4+k], p1 = Pi[4+k], p2 = Pi[8+k], p3 = Pi[12+k];
        mo[0*4+k] =  ca*p0 + sa*p1;
        mo[1*4+k] = -sa*p0 + ca*p1;
        mo[2*4+k] =  cb*p2 + sb*p3;
        mo[3*4+k] = -sb*p2 + cb*p3;
    }
}

// ---------------------------------------------------------------------------
// Kernel 3/6: SIMT SGEMM  C[m,n] = sum_k A[m,k] * W[n,k]
// BM=BN=128, BK=8, 256 threads, 8x8 microtile.
// MODE 0: A = x  (M=4096, N=3072), scatter epilogue into g_q/g_k/g_v [B,H,L,D]
// MODE 1: A = g_y (M=4096, N=1024), epilogue straight to C (d_out)
// ---------------------------------------------------------------------------
template <int MODE>
__global__ void __launch_bounds__(256) sgemm_kernel(const float* __restrict__ Ain,
                                                    const float* __restrict__ W,
                                                    float* __restrict__ C) {
    __shared__ float As[8][128];
    __shared__ float Bs[8][128];
    const float* A = (MODE == 1) ? (const float*)g_y : Ain;
    const int K = NDIM;
    int m0 = blockIdx.y * 128;
    int n0 = blockIdx.x * 128;
    int tid = threadIdx.x;
    int lr = tid >> 1;             // 0..127
    int lk = (tid & 1) * 4;        // 0 or 4
    const float* Ap = A + (size_t)(m0 + lr) * K + lk;
    const float* Wp = W + (size_t)(n0 + lr) * K + lk;

    int ty = tid >> 4, tx = tid & 15;
    float acc[8][8];
#pragma unroll
    for (int i = 0; i < 8; i++)
#pragma unroll
        for (int j = 0; j < 8; j++) acc[i][j] = 0.f;

    for (int k0 = 0; k0 < K; k0 += 8) {
        float4 av = *(const float4*)(Ap + k0);
        float4 bv = *(const float4*)(Wp + k0);
        As[lk+0][lr] = av.x; As[lk+1][lr] = av.y; As[lk+2][lr] = av.z; As[lk+3][lr] = av.w;
        Bs[lk+0][lr] = bv.x; Bs[lk+1][lr] = bv.y; Bs[lk+2][lr] = bv.z; Bs[lk+3][lr] = bv.w;
        __syncthreads();
#pragma unroll
        for (int kk = 0; kk < 8; kk++) {
            float a[8], b[8];
            *(float4*)&a[0] = *(const float4*)&As[kk][ty*8];
            *(float4*)&a[4] = *(const float4*)&As[kk][ty*8+4];
            *(float4*)&b[0] = *(const float4*)&Bs[kk][tx*8];
            *(float4*)&b[4] = *(const float4*)&Bs[kk][tx*8+4];
#pragma unroll
            for (int i = 0; i < 8; i++)
#pragma unroll
                for (int j = 0; j < 8; j++) acc[i][j] += a[i] * b[j];
        }
        __syncthreads();
    }

    if (MODE == 0) {
        int n = n0 + tx * 8;
        int t = n >> 10, r = n & 1023;
        int h = r >> 6, dh = r & 63;
        float* dstbase = (t == 0) ? g_q : (t == 1) ? g_k : g_v;
#pragma unroll
        for (int i = 0; i < 8; i++) {
            int m = m0 + ty * 8 + i;
            int bb = m >> 11, l = m & 2047;
            float* dst = dstbase + (size_t)(((bb << 4) + h) * NL + l) * ND + dh;
            *(float4*)(dst)     = make_float4(acc[i][0], acc[i][1], acc[i][2], acc[i][3]);
            *(float4*)(dst + 4) = make_float4(acc[i][4], acc[i][5], acc[i][6], acc[i][7]);
        }
    } else {
#pragma unroll
        for (int i = 0; i < 8; i++) {
            int m = m0 + ty * 8 + i;
            float* dst = C + (size_t)m * NDIM + n0 + tx * 8;
            *(float4*)(dst)     = make_float4(acc[i][0], acc[i][1], acc[i][2], acc[i][3]);
            *(float4*)(dst + 4) = make_float4(acc[i][4], acc[i][5], acc[i][6], acc[i][7]);
        }
    }
}

// ---------------------------------------------------------------------------
// Kernel 4: apply Mq to q, Mkv to k and v, in place. One thread per (b,h,l,g).
// ---------------------------------------------------------------------------
__device__ __forceinline__ float4 mat4vec(const float4 m0, const float4 m1,
                                          const float4 m2, const float4 m3, float4 t) {
    float4 o;
    o.x = m0.x*t.x + m0.y*t.y + m0.z*t.z + m0.w*t.w;
    o.y = m1.x*t.x + m1.y*t.y + m1.z*t.z + m1.w*t.w;
    o.z = m2.x*t.x + m2.y*t.y + m2.z*t.z + m2.w*t.w;
    o.w = m3.x*t.x + m3.y*t.y + m3.z*t.z + m3.w*t.w;
    return o;
}

__global__ void __launch_bounds__(256) transform_kernel() {
    int i = blockIdx.x * 256 + threadIdx.x;   // 1,048,576 total
    int g = i & 15;
    int l = (i >> 4) & 2047;
    int h = (i >> 15) & 15;
    int b = i >> 19;
    int c = l >> 8, p = l & 255;
    size_t mi  = ((size_t)(((b << 3) + c) * NPC + p) * NG + g) * 16;
    size_t off = ((size_t)(((b << 4) + h) * NL + l)) * ND + (g << 2);

    const float4* Mq4 = (const float4*)(g_Mq + mi);
    float4 a0 = Mq4[0], a1 = Mq4[1], a2 = Mq4[2], a3 = Mq4[3];
    float4 qv = *(float4*)(g_q + off);
    *(float4*)(g_q + off) = mat4vec(a0, a1, a2, a3, qv);

    const float4* Mk4 = (const float4*)(g_Mkv + mi);
    float4 b0 = Mk4[0], b1 = Mk4[1], b2 = Mk4[2], b3 = Mk4[3];
    float4 kv = *(float4*)(g_k + off);
    *(float4*)(g_k + off) = mat4vec(b0, b1, b2, b3, kv);
    float4 vv = *(float4*)(g_v + off);
    *(float4*)(g_v + off) = mat4vec(b0, b1, b2, b3, vv);
}

// ---------------------------------------------------------------------------
// Kernel 5: flash attention, 64 queries x 64 keys tiles, fp32, online softmax.
// 256 threads = 16x16, 4x4 microtile. Mo fused into epilogue (thread's 4 cols
// = one RoPE group). Writes [B, L, H*D] ready for the projection GEMM.
// ---------------------------------------------------------------------------
#define SPITCH 68
__global__ void __launch_bounds__(256) attn_kernel() {
    extern __shared__ float sm[];
    float* Qts = sm;                     // [64][SPITCH]  d-major
    float* Kts = sm + 64 * SPITCH;       // [64][SPITCH]  d-major
    float* Vs  = sm + 2 * 64 * SPITCH;   // [64][SPITCH]  j-major
    float* Pts = sm + 3 * 64 * SPITCH;   // [64][SPITCH]  j-major

    int bh = blockIdx.y;
    int b = bh >> 4, h = bh & 15;
    int l0 = blockIdx.x * 64;
    int tid = threadIdx.x;
    int ty = tid >> 4, tx = tid & 15;

    // load + transpose Q tile, fold in softmax scale 1/sqrt(64)
    const float* Qg = g_q + (size_t)(bh * NL + l0) * ND;
    for (int i = tid; i < 64 * 16; i += 256) {
        int r = i >> 4, d4 = (i & 15) << 2;
        float4 q = *(const float4*)(Qg + r * ND + d4);
        Qts[(d4+0)*SPITCH + r] = q.x * 0.125f;
        Qts[(d4+1)*SPITCH + r] = q.y * 0.125f;
        Qts[(d4+2)*SPITCH + r] = q.z * 0.125f;
        Qts[(d4+3)*SPITCH + r] = q.w * 0.125f;
    }

    float acc[4][4];
#pragma unroll
    for (int i = 0; i < 4; i++)
#pragma unroll
        for (int j = 0; j < 4; j++) acc[i][j] = 0.f;
    float mi[4] = {-1e30f, -1e30f, -1e30f, -1e30f};
    float li[4] = {0.f, 0.f, 0.f, 0.f};

    for (int kt = 0; kt < NL; kt += 64) {
        const float* Kg = g_k + (size_t)(bh * NL + kt) * ND;
        const float* Vg = g_v + (size_t)(bh * NL + kt) * ND;
        __syncthreads();   // prev iter's PV done (and Q visible on iter 0 after next sync)
        for (int i = tid; i < 64 * 16; i += 256) {
            int r = i >> 4, d4 = (i & 15) << 2;
            float4 kv = *(const float4*)(Kg + r * ND + d4);
            Kts[(d4+0)*SPITCH + r] = kv.x;
            Kts[(d4+1)*SPITCH + r] = kv.y;
            Kts[(d4+2)*SPITCH + r] = kv.z;
            Kts[(d4+3)*SPITCH + r] = kv.w;
            float4 vv = *(const float4*)(Vg + r * ND + d4);
            *(float4*)(Vs + r * SPITCH + d4) = vv;
        }
        __syncthreads();

        // S = Q K^T (scaled)
        float s[4][4];
#pragma unroll
        for (int i = 0; i < 4; i++)
#pragma unroll
            for (int j = 0; j < 4; j++) s[i][j] = 0.f;
#pragma unroll 8
        for (int d = 0; d < 64; d++) {
            float4 a = *(const float4*)(Qts + d * SPITCH + ty * 4);
            float4 bq = *(const float4*)(Kts + d * SPITCH + tx * 4);
            float av[4] = {a.x, a.y, a.z, a.w};
            float bv[4] = {bq.x, bq.y, bq.z, bq.w};
#pragma unroll
            for (int i = 0; i < 4; i++)
#pragma unroll
                for (int j = 0; j < 4; j++) s[i][j] += av[i] * bv[j];
        }

        // online softmax
        float rmax[4], rsum[4], al[4];
#pragma unroll
        for (int i = 0; i < 4; i++) {
            rmax[i] = fmaxf(fmaxf(s[i][0], s[i][1]), fmaxf(s[i][2], s[i][3]));
#pragma unroll
            for (int off = 8; off > 0; off >>= 1)
                rmax[i] = fmaxf(rmax[i], __shfl_xor_sync(0xffffffffu, rmax[i], off));
            float mn = fmaxf(mi[i], rmax[i]);
            al[i] = expf(mi[i] - mn);
            mi[i] = mn;
            rsum[i] = 0.f;
#pragma unroll
            for (int j = 0; j < 4; j++) {
                float pv = expf(s[i][j] - mn);
                s[i][j] = pv;
                rsum[i] += pv;
            }
#pragma unroll
            for (int off = 8; off > 0; off >>= 1)
                rsum[i] += __shfl_xor_sync(0xffffffffu, rsum[i], off);
            li[i] = li[i] * al[i] + rsum[i];
#pragma unroll
            for (int j = 0; j < 4; j++) acc[i][j] *= al[i];
        }

        // P -> shared (transposed: Pts[col][row])
#pragma unroll
        for (int i = 0; i < 4; i++)
#pragma unroll
            for (int j = 0; j < 4; j++)
                Pts[(tx*4 + j) * SPITCH + ty*4 + i] = s[i][j];
        __syncthreads();

        // O += P V
#pragma unroll 8
        for (int d = 0; d < 64; d++) {
            float4 a = *(const float4*)(Pts + d * SPITCH + ty * 4);
            float4 bv4 = *(const float4*)(Vs + d * SPITCH + tx * 4);
            float av[4] = {a.x, a.y, a.z, a.w};
            float bv[4] = {bv4.x, bv4.y, bv4.z, bv4.w};
#pragma unroll
            for (int i = 0; i < 4; i++)
#pragma unroll
                for (int j = 0; j < 4; j++) acc[i][j] += av[i] * bv[j];
        }
    }

    // epilogue: normalize, apply Mo (group = tx), write [B, L, H*64]
#pragma unroll
    for (int i = 0; i < 4; i++) {
        int l = l0 + ty * 4 + i;
        int c = l >> 8, p = l & 255;
        const float* Mo = g_Mo + ((size_t)(((b << 3) + c) * NPC + p) * NG + tx) * 16;
        float inv = 1.0f / li[i];
        float o0 = acc[i][0] * inv, o1 = acc[i][1] * inv;
        float o2 = acc[i][2] * inv, o3 = acc[i][3] * inv;
        float4 r;
        r.x = Mo[0]*o0  + Mo[1]*o1  + Mo[2]*o2  + Mo[3]*o3;
        r.y = Mo[4]*o0  + Mo[5]*o1  + Mo[6]*o2  + Mo[7]*o3;
        r.z = Mo[8]*o0  + Mo[9]*o1  + Mo[10]*o2 + Mo[11]*o3;
        r.w = Mo[12]*o0 + Mo[13]*o1 + Mo[14]*o2 + Mo[15]*o3;
        *(float4*)(g_y + (size_t)(b * NL + l) * NDIM + h * ND + tx * 4) = r;
    }
}

// ---------------------------------------------------------------------------
extern "C" void kernel_launch(void* const* d_in, const int* in_sizes, int n_in,
                              void* d_out, int out_size) {
    const float* x     = (const float*)d_in[0];
    const float* vm    = (const float*)d_in[1];
    const float* Ks    = (const float*)d_in[2];
    const float* wqkv  = (const float*)d_in[3];
    const float* wproj = (const float*)d_in[4];
    float* out = (float*)d_out;

    const int ATTN_SMEM = 4 * 64 * SPITCH * (int)sizeof(float);  // 69632 B
    cudaFuncSetAttribute(attn_kernel, cudaFuncAttributeMaxDynamicSharedMemorySize, ATTN_SMEM);

    cam_kernel<<<1, 32>>>(vm, Ks);
    m_kernel<<<256, 256>>>();
    sgemm_kernel<0><<<dim3(24, 32), 256>>>(x, wqkv, nullptr);
    transform_kernel<<<4096, 256>>>();
    attn_kernel<<<dim3(32, 32), 256, ATTN_SMEM>>>();
    sgemm_kernel<1><<<dim3(8, 32), 256>>>(nullptr, wproj, out);
}

// round 4
// speedup vs baseline: 1.3743x; 1.3743x over previous
#include <cuda_runtime.h>
#include <cuda_bf16.h>
#include <math.h>
#include <stdint.h>

// Problem constants
#define NB    2
#define NL    2048
#define NH    16
#define ND    64
#define NDIM  1024
#define NC    8
#define NPC   256
#define NG    16
#define NBC   (NB*NC)

// Scratch (device globals; no allocation allowed)
__device__ float g_q  [NB*NH*NL*ND];
__device__ float g_k  [NB*NH*NL*ND];
__device__ float g_v  [NB*NH*NL*ND];
__device__ float g_Mq [NBC*NPC*NG*16];
__device__ float g_Mkv[NBC*NPC*NG*16];
__device__ float g_Mo [NBC*NPC*NG*16];
__device__ float g_P  [NBC*16];
__device__ float g_Pi [NBC*16];
__device__ float g_y  [NB*NL*NDIM];

// bf16 hi/lo split buffers: per 32-float chunk -> [32 hi bf16 | 32 lo bf16] = 128B
__device__ __align__(128) __nv_bfloat16 g_xs [4096*2048];   // x split
__device__ __align__(128) __nv_bfloat16 g_wqs[3072*2048];   // w_qkv split
__device__ __align__(128) __nv_bfloat16 g_wps[1024*2048];   // w_proj split
__device__ __align__(128) __nv_bfloat16 g_ys [4096*2048];   // y split

// ---------------------------------------------------------------------------
// PTX helpers (sm_103-safe: mma.sync / ldmatrix / cp.async only)
// ---------------------------------------------------------------------------
__device__ __forceinline__ uint32_t smem_u32(const void* p) {
    uint32_t a;
    asm("{ .reg .u64 t; cvta.to.shared.u64 t, %1; cvt.u32.u64 %0, t; }" : "=r"(a) : "l"(p));
    return a;
}
__device__ __forceinline__ void cpa16(uint32_t sdst, const void* gsrc) {
    asm volatile("cp.async.cg.shared.global [%0], [%1], 16;" :: "r"(sdst), "l"(gsrc) : "memory");
}
#define CP_COMMIT() asm volatile("cp.async.commit_group;" ::: "memory")
#define CP_WAIT(n)  asm volatile("cp.async.wait_group %0;" :: "n"(n) : "memory")

__device__ __forceinline__ void ldsm_x4(uint32_t addr, uint32_t* r) {
    asm volatile("ldmatrix.sync.aligned.m8n8.x4.shared.b16 {%0,%1,%2,%3}, [%4];"
        : "=r"(r[0]), "=r"(r[1]), "=r"(r[2]), "=r"(r[3]) : "r"(addr));
}
__device__ __forceinline__ void mma16816(float* c, const uint32_t* a, uint32_t b0, uint32_t b1) {
    asm volatile("mma.sync.aligned.m16n8k16.row.col.f32.bf16.bf16.f32 "
        "{%0,%1,%2,%3}, {%4,%5,%6,%7}, {%8,%9}, {%0,%1,%2,%3};"
        : "+f"(c[0]), "+f"(c[1]), "+f"(c[2]), "+f"(c[3])
        : "r"(a[0]), "r"(a[1]), "r"(a[2]), "r"(a[3]), "r"(b0), "r"(b1));
}

// ---------------------------------------------------------------------------
// Kernel 1: per-camera P = K4 @ viewmat and analytic P^{-1}
// ---------------------------------------------------------------------------
__global__ void cam_kernel(const float* __restrict__ vm, const float* __restrict__ Kin) {
    int t = threadIdx.x;
    if (t >= NBC) return;
    const float* V = vm + t * 16;
    const float* K = Kin + t * 9;
    float P[16];
#pragma unroll
    for (int i = 0; i < 3; i++)
#pragma unroll
        for (int j = 0; j < 4; j++)
            P[i*4+j] = K[i*3+0]*V[0+j] + K[i*3+1]*V[4+j] + K[i*3+2]*V[8+j];
    P[12] = V[12]; P[13] = V[13]; P[14] = V[14]; P[15] = V[15];

    float Vi[16];
#pragma unroll
    for (int i = 0; i < 3; i++) {
#pragma unroll
        for (int j = 0; j < 3; j++) Vi[i*4+j] = V[j*4+i];
        Vi[i*4+3] = -(V[0*4+i]*V[3] + V[1*4+i]*V[7] + V[2*4+i]*V[11]);
    }
    Vi[12] = 0.f; Vi[13] = 0.f; Vi[14] = 0.f; Vi[15] = 1.f;

    float f = K[0], cx = K[2], cy = K[5];
    float invf = 1.0f / f;
    float Pi[16];
#pragma unroll
    for (int i = 0; i < 4; i++) {
        float c0 = Vi[i*4+0] * invf;
        float c1 = Vi[i*4+1] * invf;
        Pi[i*4+0] = c0;
        Pi[i*4+1] = c1;
        Pi[i*4+2] = Vi[i*4+2] - cx*c0 - cy*c1;
        Pi[i*4+3] = Vi[i*4+3];
    }
#pragma unroll
    for (int i = 0; i < 16; i++) { g_P[t*16+i] = P[i]; g_Pi[t*16+i] = Pi[i]; }
}

// ---------------------------------------------------------------------------
// Kernel 2: per-(b,c,p,g) transforms Mq, Mkv, Mo
// ---------------------------------------------------------------------------
__global__ void m_kernel() {
    int i = blockIdx.x * blockDim.x + threadIdx.x;
    int g  = i & 15;
    int p  = (i >> 4) & 255;
    int bc = i >> 12;
    const float* P  = g_P  + bc * 16;
    const float* Pi = g_Pi + bc * 16;

    float u = ((p & 15) + 0.5f) * 16.0f;
    float v = ((p >> 4) + 0.5f) * 16.0f;
    float fr = powf(10000.0f, -(float)g / 16.0f);
    float sa, ca, sb, cb;
    sincosf(u * fr, &sa, &ca);
    sincosf(v * fr, &sb, &cb);

    float* mq  = g_Mq  + i * 16;
    float* mkv = g_Mkv + i * 16;
    float* mo  = g_Mo  + i * 16;
#pragma unroll
    for (int r = 0; r < 4; r++) {
        float p0 = Pi[0*4+r], p1 = Pi[1*4+r], p2 = Pi[2*4+r], p3 = Pi[3*4+r];
        mq[r*4+0] =  p0*ca + p1*sa;
        mq[r*4+1] = -p0*sa + p1*ca;
        mq[r*4+2] =  p2*cb + p3*sb;
        mq[r*4+3] = -p2*sb + p3*cb;
        float q0 = P[r*4+0], q1 = P[r*4+1], q2 = P[r*4+2], q3 = P[r*4+3];
        mkv[r*4+0] =  q0*ca + q1*sa;
        mkv[r*4+1] = -q0*sa + q1*ca;
        mkv[r*4+2] =  q2*cb + q3*sb;
        mkv[r*4+3] = -q2*sb + q3*cb;
    }
#pragma unroll
    for (int k = 0; k < 4; k++) {
        float p0 = Pi[0*4+k], p1 = Pi[4+k], p2 = Pi[8+k], p3 = Pi[12+k];
        mo[0*4+k] =  ca*p0 + sa*p1;
        mo[1*4+k] = -sa*p0 + ca*p1;
        mo[2*4+k] =  cb*p2 + sb*p3;
        mo[3*4+k] = -sb*p2 + cb*p3;
    }
}

// ---------------------------------------------------------------------------
// bf16 hi/lo split: per 32-float chunk -> [hi x32 | lo x32] bf16 (128 bytes)
// ---------------------------------------------------------------------------
__global__ void __launch_bounds__(256) split_kernel(const float* __restrict__ src,
                                                    __nv_bfloat16* __restrict__ dst, int nchunks) {
    int c = blockIdx.x * 256 + threadIdx.x;
    if (c >= nchunks) return;
    const float4* s = (const float4*)src + (size_t)c * 8;
    __nv_bfloat162 H[16], L[16];
#pragma unroll
    for (int i = 0; i < 8; i++) {
        float4 f = s[i];
        float vv[4] = {f.x, f.y, f.z, f.w};
#pragma unroll
        for (int j = 0; j < 2; j++) {
            float a = vv[2*j], b = vv[2*j+1];
            __nv_bfloat16 ha = __float2bfloat16_rn(a);
            __nv_bfloat16 hb = __float2bfloat16_rn(b);
            __nv_bfloat16 la = __float2bfloat16_rn(a - __bfloat162float(ha));
            __nv_bfloat16 lb = __float2bfloat16_rn(b - __bfloat162float(hb));
            H[i*2+j] = __halves2bfloat162(ha, hb);
            L[i*2+j] = __halves2bfloat162(la, lb);
        }
    }
    uint4* d = (uint4*)(dst + (size_t)c * 64);
    const uint4* hv = (const uint4*)H;
    const uint4* lv = (const uint4*)L;
#pragma unroll
    for (int i = 0; i < 4; i++) d[i] = hv[i];
#pragma unroll
    for (int i = 0; i < 4; i++) d[4+i] = lv[i];
}

// ---------------------------------------------------------------------------
// mma.sync split-bf16 GEMM: C[m,n] = sum_k A[m,k]*W[n,k], K=1024.
// BM=128, BN=128, chunk = 32 floats (128B hi|lo per row). 4-stage cp.async.
// 8 warps, warp tile 32x64. MODE 0: scatter q/k/v. MODE 1: write Cout.
// ---------------------------------------------------------------------------
#define GS        4
#define GSTAGE_B  32768           // A 16KB + B 16KB
#define GSM_TOTAL (GS*GSTAGE_B)   // 131072

// smem addr for (row, 16B-seg) in a 128-row x 128B tile with per-row swizzle
__device__ __forceinline__ uint32_t sw_addr(uint32_t base, int row, int seg) {
    return base + row * 128 + ((seg ^ (row & 7)) << 4);
}

__device__ __forceinline__ void g_load_stage(uint32_t sA, uint32_t sB,
        const char* Ab, const char* Bb, int m0, int n0, int kc, int tid) {
#pragma unroll
    for (int it = 0; it < 4; it++) {
        int u = tid + it * 256;
        int r = u >> 3, s = u & 7;
        cpa16(sw_addr(sA, r, s), Ab + ((size_t)(m0 + r) * 32 + kc) * 128 + s * 16);
    }
#pragma unroll
    for (int it = 0; it < 4; it++) {
        int u = tid + it * 256;
        int r = u >> 3, s = u & 7;
        cpa16(sw_addr(sB, r, s), Bb + ((size_t)(n0 + r) * 32 + kc) * 128 + s * 16);
    }
}

template <int MODE>
__global__ void __launch_bounds__(256) gemm_mma(const __nv_bfloat16* __restrict__ Abf,
                                                const __nv_bfloat16* __restrict__ Bbf,
                                                float* __restrict__ q, float* __restrict__ k,
                                                float* __restrict__ v, float* __restrict__ Cout) {
    extern __shared__ char smem[];
    uint32_t sb = smem_u32(smem);
    int tid = threadIdx.x, wid = tid >> 5, lane = tid & 31;
    int m0 = blockIdx.y * 128, n0 = blockIdx.x * 128;
    const char* Ab = (const char*)Abf;
    const char* Bb = (const char*)Bbf;

    int wm = (wid & 3) * 32;       // warp m offset (0,32,64,96)
    int wn = (wid >> 2) * 64;      // warp n offset (0,64)
    int lrow = lane & 7;
    int lm8  = (lane >> 3) & 1;    // +8 row within 16-tile
    int lk   = lane >> 4;          // +1 seg (k 8..15 half)

    float acc[2][8][4];
#pragma unroll
    for (int t = 0; t < 2; t++)
#pragma unroll
        for (int g = 0; g < 8; g++)
#pragma unroll
            for (int r = 0; r < 4; r++) acc[t][g][r] = 0.f;

    // prologue: prefetch GS-1 stages
#pragma unroll
    for (int s = 0; s < GS - 1; s++) {
        uint32_t sA = sb + s * GSTAGE_B;
        g_load_stage(sA, sA + 16384, Ab, Bb, m0, n0, s, tid);
        CP_COMMIT();
    }

    // k16-step (A-seg, B-seg) schedule: hi=segs 0..3, lo=segs 4..7
    const int stepA[6] = {0, 2, 0, 2, 4, 6};
    const int stepB[6] = {0, 2, 4, 6, 0, 2};

    for (int i = 0; i < 32; i++) {
        CP_WAIT(GS - 2);
        __syncthreads();
        uint32_t sA = sb + (i & (GS - 1)) * GSTAGE_B;
        uint32_t sB = sA + 16384;
#pragma unroll
        for (int st = 0; st < 6; st++) {
            int sa0 = stepA[st], sb0 = stepB[st];
            uint32_t a[2][4];
#pragma unroll
            for (int t = 0; t < 2; t++) {
                int row = wm + t * 16 + lm8 * 8 + lrow;
                ldsm_x4(sw_addr(sA, row, sa0 + lk), a[t]);
            }
            uint32_t b[4][4];
#pragma unroll
            for (int g = 0; g < 4; g++) {
                int row = wn + g * 16 + lm8 * 8 + lrow;
                ldsm_x4(sw_addr(sB, row, sb0 + lk), b[g]);
            }
#pragma unroll
            for (int t = 0; t < 2; t++)
#pragma unroll
                for (int g = 0; g < 4; g++) {
                    mma16816(acc[t][2*g],   a[t], b[g][0], b[g][2]);
                    mma16816(acc[t][2*g+1], a[t], b[g][1], b[g][3]);
                }
        }
        __syncthreads();
        if (i + GS - 1 < 32) {
            uint32_t dA = sb + ((i + GS - 1) & (GS - 1)) * GSTAGE_B;
            g_load_stage(dA, dA + 16384, Ab, Bb, m0, n0, i + GS - 1, tid);
        }
        CP_COMMIT();
    }

    // epilogue
    int mrow = (lane >> 2);
    int ncol = (lane & 3) * 2;
#pragma unroll
    for (int t = 0; t < 2; t++) {
#pragma unroll
        for (int g = 0; g < 8; g++) {
            int n = n0 + wn + (g >> 1) * 16 + (g & 1) * 8 + ncol;
            int m = m0 + wm + t * 16 + mrow;
#pragma unroll
            for (int half = 0; half < 2; half++) {
                int mm = m + half * 8;
                float* dst;
                if (MODE == 0) {
                    int tt = n >> 10;
                    float* base = (tt == 0) ? q : (tt == 1) ? k : v;
                    int h = (n >> 6) & 15;
                    int bb = mm >> 11, l = mm & 2047;
                    dst = base + ((size_t)((bb << 4) + h) * NL + l) * ND + (n & 63);
                } else {
                    dst = Cout + (size_t)mm * NDIM + n;
                }
                *(float2*)dst = make_float2(acc[t][g][half*2], acc[t][g][half*2+1]);
            }
        }
    }
}

// ---------------------------------------------------------------------------
// Kernel 4: apply Mq to q, Mkv to k and v, in place.
// ---------------------------------------------------------------------------
__device__ __forceinline__ float4 mat4vec(const float4 m0, const float4 m1,
                                          const float4 m2, const float4 m3, float4 t) {
    float4 o;
    o.x = m0.x*t.x + m0.y*t.y + m0.z*t.z + m0.w*t.w;
    o.y = m1.x*t.x + m1.y*t.y + m1.z*t.z + m1.w*t.w;
    o.z = m2.x*t.x + m2.y*t.y + m2.z*t.z + m2.w*t.w;
    o.w = m3.x*t.x + m3.y*t.y + m3.z*t.z + m3.w*t.w;
    return o;
}

__global__ void __launch_bounds__(256) transform_kernel() {
    int i = blockIdx.x * 256 + threadIdx.x;
    int g = i & 15;
    int l = (i >> 4) & 2047;
    int h = (i >> 15) & 15;
    int b = i >> 19;
    int c = l >> 8, p = l & 255;
    size_t mi  = ((size_t)(((b << 3) + c) * NPC + p) * NG + g) * 16;
    size_t off = ((size_t)(((b << 4) + h) * NL + l)) * ND + (g << 2);

    const float4* Mq4 = (const float4*)(g_Mq + mi);
    float4 a0 = Mq4[0], a1 = Mq4[1], a2 = Mq4[2], a3 = Mq4[3];
    float4 qv = *(float4*)(g_q + off);
    *(float4*)(g_q + off) = mat4vec(a0, a1, a2, a3, qv);

    const float4* Mk4 = (const float4*)(g_Mkv + mi);
    float4 b0 = Mk4[0], b1 = Mk4[1], b2 = Mk4[2], b3 = Mk4[3];
    float4 kv = *(float4*)(g_k + off);
    *(float4*)(g_k + off) = mat4vec(b0, b1, b2, b3, kv);
    float4 vv = *(float4*)(g_v + off);
    *(float4*)(g_v + off) = mat4vec(b0, b1, b2, b3, vv);
}

// ---------------------------------------------------------------------------
// Kernel 5: flash attention (fp32 SIMT), Mo fused into epilogue.
// ---------------------------------------------------------------------------
#define SPITCH 68
__global__ void __launch_bounds__(256) attn_kernel() {
    extern __shared__ float sm[];
    float* Qts = sm;
    float* Kts = sm + 64 * SPITCH;
    float* Vs  = sm + 2 * 64 * SPITCH;
    float* Pts = sm + 3 * 64 * SPITCH;

    int bh = blockIdx.y;
    int b = bh >> 4, h = bh & 15;
    int l0 = blockIdx.x * 64;
    int tid = threadIdx.x;
    int ty = tid >> 4, tx = tid & 15;

    const float* Qg = g_q + (size_t)(bh * NL + l0) * ND;
    for (int i = tid; i < 64 * 16; i += 256) {
        int r = i >> 4, d4 = (i & 15) << 2;
        float4 qv = *(const float4*)(Qg + r * ND + d4);
        Qts[(d4+0)*SPITCH + r] = qv.x * 0.125f;
        Qts[(d4+1)*SPITCH + r] = qv.y * 0.125f;
        Qts[(d4+2)*SPITCH + r] = qv.z * 0.125f;
        Qts[(d4+3)*SPITCH + r] = qv.w * 0.125f;
    }

    float acc[4][4];
#pragma unroll
    for (int i = 0; i < 4; i++)
#pragma unroll
        for (int j = 0; j < 4; j++) acc[i][j] = 0.f;
    float mi[4] = {-1e30f, -1e30f, -1e30f, -1e30f};
    float li[4] = {0.f, 0.f, 0.f, 0.f};

    for (int kt = 0; kt < NL; kt += 64) {
        const float* Kg = g_k + (size_t)(bh * NL + kt) * ND;
        const float* Vg = g_v + (size_t)(bh * NL + kt) * ND;
        __syncthreads();
        for (int i = tid; i < 64 * 16; i += 256) {
            int r = i >> 4, d4 = (i & 15) << 2;
            float4 kv = *(const float4*)(Kg + r * ND + d4);
            Kts[(d4+0)*SPITCH + r] = kv.x;
            Kts[(d4+1)*SPITCH + r] = kv.y;
            Kts[(d4+2)*SPITCH + r] = kv.z;
            Kts[(d4+3)*SPITCH + r] = kv.w;
            float4 vv = *(const float4*)(Vg + r * ND + d4);
            *(float4*)(Vs + r * SPITCH + d4) = vv;
        }
        __syncthreads();

        float s[4][4];
#pragma unroll
        for (int i = 0; i < 4; i++)
#pragma unroll
            for (int j = 0; j < 4; j++) s[i][j] = 0.f;
#pragma unroll 8
        for (int d = 0; d < 64; d++) {
            float4 a = *(const float4*)(Qts + d * SPITCH + ty * 4);
            float4 bq = *(const float4*)(Kts + d * SPITCH + tx * 4);
            float av[4] = {a.x, a.y, a.z, a.w};
            float bv[4] = {bq.x, bq.y, bq.z, bq.w};
#pragma unroll
            for (int i = 0; i < 4; i++)
#pragma unroll
                for (int j = 0; j < 4; j++) s[i][j] += av[i] * bv[j];
        }

        float rmax[4], rsum[4], al[4];
#pragma unroll
        for (int i = 0; i < 4; i++) {
            rmax[i] = fmaxf(fmaxf(s[i][0], s[i][1]), fmaxf(s[i][2], s[i][3]));
#pragma unroll
            for (int off = 8; off > 0; off >>= 1)
                rmax[i] = fmaxf(rmax[i], __shfl_xor_sync(0xffffffffu, rmax[i], off));
            float mn = fmaxf(mi[i], rmax[i]);
            al[i] = expf(mi[i] - mn);
            mi[i] = mn;
            rsum[i] = 0.f;
#pragma unroll
            for (int j = 0; j < 4; j++) {
                float pv = expf(s[i][j] - mn);
                s[i][j] = pv;
                rsum[i] += pv;
            }
#pragma unroll
            for (int off = 8; off > 0; off >>= 1)
                rsum[i] += __shfl_xor_sync(0xffffffffu, rsum[i], off);
            li[i] = li[i] * al[i] + rsum[i];
#pragma unroll
            for (int j = 0; j < 4; j++) acc[i][j] *= al[i];
        }

#pragma unroll
        for (int i = 0; i < 4; i++)
#pragma unroll
            for (int j = 0; j < 4; j++)
                Pts[(tx*4 + j) * SPITCH + ty*4 + i] = s[i][j];
        __syncthreads();

#pragma unroll 8
        for (int d = 0; d < 64; d++) {
            float4 a = *(const float4*)(Pts + d * SPITCH + ty * 4);
            float4 bv4 = *(const float4*)(Vs + d * SPITCH + tx * 4);
            float av[4] = {a.x, a.y, a.z, a.w};
            float bv[4] = {bv4.x, bv4.y, bv4.z, bv4.w};
#pragma unroll
            for (int i = 0; i < 4; i++)
#pragma unroll
                for (int j = 0; j < 4; j++) acc[i][j] += av[i] * bv[j];
        }
    }

#pragma unroll
    for (int i = 0; i < 4; i++) {
        int l = l0 + ty * 4 + i;
        int c = l >> 8, p = l & 255;
        const float* Mo = g_Mo + ((size_t)(((b << 3) + c) * NPC + p) * NG + tx) * 16;
        float inv = 1.0f / li[i];
        float o0 = acc[i][0] * inv, o1 = acc[i][1] * inv;
        float o2 = acc[i][2] * inv, o3 = acc[i][3] * inv;
        float4 r;
        r.x = Mo[0]*o0  + Mo[1]*o1  + Mo[2]*o2  + Mo[3]*o3;
        r.y = Mo[4]*o0  + Mo[5]*o1  + Mo[6]*o2  + Mo[7]*o3;
        r.z = Mo[8]*o0  + Mo[9]*o1  + Mo[10]*o2 + Mo[11]*o3;
        r.w = Mo[12]*o0 + Mo[13]*o1 + Mo[14]*o2 + Mo[15]*o3;
        *(float4*)(g_y + (size_t)(b * NL + l) * NDIM + h * ND + tx * 4) = r;
    }
}

// ---------------------------------------------------------------------------
extern "C" void kernel_launch(void* const* d_in, const int* in_sizes, int n_in,
                              void* d_out, int out_size) {
    const float* x     = (const float*)d_in[0];
    const float* vm    = (const float*)d_in[1];
    const float* Ks    = (const float*)d_in[2];
    const float* wqkv  = (const float*)d_in[3];
    const float* wproj = (const float*)d_in[4];
    float* out = (float*)d_out;

    void *p_xs, *p_wqs, *p_wps, *p_ys, *p_y, *p_q, *p_k, *p_v;
    cudaGetSymbolAddress(&p_xs,  g_xs);
    cudaGetSymbolAddress(&p_wqs, g_wqs);
    cudaGetSymbolAddress(&p_wps, g_wps);
    cudaGetSymbolAddress(&p_ys,  g_ys);
    cudaGetSymbolAddress(&p_y,   g_y);
    cudaGetSymbolAddress(&p_q,   g_q);
    cudaGetSymbolAddress(&p_k,   g_k);
    cudaGetSymbolAddress(&p_v,   g_v);

    const int ATTN_SMEM = 4 * 64 * SPITCH * (int)sizeof(float);
    cudaFuncSetAttribute(attn_kernel, cudaFuncAttributeMaxDynamicSharedMemorySize, ATTN_SMEM);
    cudaFuncSetAttribute(gemm_mma<0>, cudaFuncAttributeMaxDynamicSharedMemorySize, GSM_TOTAL);
    cudaFuncSetAttribute(gemm_mma<1>, cudaFuncAttributeMaxDynamicSharedMemorySize, GSM_TOTAL);

    cam_kernel<<<1, 32>>>(vm, Ks);
    m_kernel<<<256, 256>>>();
    split_kernel<<<512, 256>>>(x,     (__nv_bfloat16*)p_xs,  4096 * 32);
    split_kernel<<<384, 256>>>(wqkv,  (__nv_bfloat16*)p_wqs, 3072 * 32);
    split_kernel<<<128, 256>>>(wproj, (__nv_bfloat16*)p_wps, 1024 * 32);
    gemm_mma<0><<<dim3(24, 32), 256, GSM_TOTAL>>>((const __nv_bfloat16*)p_xs, (const __nv_bfloat16*)p_wqs,
                                                  (float*)p_q, (float*)p_k, (float*)p_v, nullptr);
    transform_kernel<<<4096, 256>>>();
    attn_kernel<<<dim3(32, 32), 256, ATTN_SMEM>>>();
    split_kernel<<<512, 256>>>((const float*)p_y, (__nv_bfloat16*)p_ys, 4096 * 32);
    gemm_mma<1><<<dim3(8, 32), 256, GSM_TOTAL>>>((const __nv_bfloat16*)p_ys, (const __nv_bfloat16*)p_wps,
                                                 nullptr, nullptr, nullptr, out);
}